// round 15
// baseline (speedup 1.0000x reference)
#include <cuda_runtime.h>
#include <cuda_fp16.h>
#include <math.h>
#include <stdint.h>

// ---------------- problem dims ----------------
#define BATCH   8
#define SEQ     512
#define NTOK    4096
#define DMODEL  1024
#define NHEAD   16
#define DHEAD   64
#define DFF     4096
#define NLAYER  6
#define KVW     2048
#define QKVW    3072

typedef __half fp16;

// ---------------- scratch ----------------
__device__ float g_x [(size_t)NTOK * DMODEL];
__device__ float g_pe[(size_t)SEQ * DMODEL];

__device__ fp16 g_qkv16[(size_t)NTOK * QKVW];
__device__ fp16 g_h16[(size_t)NTOK * DMODEL];
__device__ fp16 g_o16[(size_t)NTOK * DMODEL];
__device__ fp16 g_f16[(size_t)NTOK * DFF];

// transposed weights: [N,K] fp16
__device__ fp16 g_wqkvT[(size_t)NLAYER * DMODEL * QKVW];
__device__ fp16 g_woT [(size_t)NLAYER * DMODEL * DMODEL];
__device__ fp16 g_w1T [(size_t)NLAYER * DMODEL * DFF];
__device__ fp16 g_w2T [(size_t)NLAYER * DFF * DMODEL];
__device__ float g_bqkv[(size_t)NLAYER * QKVW];

// ---------------- helpers ----------------
__device__ __forceinline__ uint32_t smem_u32(const void* p) {
    uint32_t a;
    asm("{ .reg .u64 t; cvta.to.shared.u64 t, %1; cvt.u32.u64 %0, t; }" : "=r"(a) : "l"(p));
    return a;
}
#define CP_ASYNC16(dst, src) \
    asm volatile("cp.async.cg.shared.global [%0], [%1], 16;" :: "r"(dst), "l"(src) : "memory")
#define CP_COMMIT() asm volatile("cp.async.commit_group;" ::: "memory")
#define CP_WAIT2()  asm volatile("cp.async.wait_group 2;" ::: "memory")
#define CP_WAIT1()  asm volatile("cp.async.wait_group 1;" ::: "memory")
#define CP_WAIT0()  asm volatile("cp.async.wait_group 0;" ::: "memory")

__device__ __forceinline__ void ldsm4(uint32_t* r, uint32_t addr) {
    asm volatile("ldmatrix.sync.aligned.m8n8.x4.shared.b16 {%0,%1,%2,%3}, [%4];"
        : "=r"(r[0]), "=r"(r[1]), "=r"(r[2]), "=r"(r[3]) : "r"(addr));
}
__device__ __forceinline__ void ldsm4t(uint32_t* r, uint32_t addr) {
    asm volatile("ldmatrix.sync.aligned.m8n8.x4.trans.shared.b16 {%0,%1,%2,%3}, [%4];"
        : "=r"(r[0]), "=r"(r[1]), "=r"(r[2]), "=r"(r[3]) : "r"(addr));
}
__device__ __forceinline__ void mma_f16(float* d, const uint32_t* a, const uint32_t* b) {
    asm volatile("mma.sync.aligned.m16n8k16.row.col.f32.f16.f16.f32 "
        "{%0,%1,%2,%3}, {%4,%5,%6,%7}, {%8,%9}, {%0,%1,%2,%3};"
        : "+f"(d[0]), "+f"(d[1]), "+f"(d[2]), "+f"(d[3])
        : "r"(a[0]), "r"(a[1]), "r"(a[2]), "r"(a[3]), "r"(b[0]), "r"(b[1]));
}
__device__ __forceinline__ uint32_t pack_h2(float a, float b) {
    __half2 h = __halves2half2(__float2half_rn(a), __float2half_rn(b));
    return *(uint32_t*)&h;
}

// ---------------- fp16 1-pass GEMM: C[M,N] = A @ Bt^T ----------------
// CTA 128x256, 8 warps (2x4), warp tile 64x64, BK=64, 4-stage cp.async,
// ONE barrier per iteration (loads issued post-sync; stage (it+3)%4==(it-1)%4 drained).
// MODE 1: fp32 +residual+bias; 2: relu -> fp16; 3: fp16
#define ROWB   144
#define OFF_A  0
#define OFF_B  18432
#define STAGE  55296
#define NSTAGE 4
#define SMEM_T (NSTAGE * STAGE)

template <int MODE>
__global__ void __launch_bounds__(256) tgemm(const fp16* __restrict__ Aa,
                                             const fp16* __restrict__ Bw,
                                             const float* __restrict__ bias,
                                             float* __restrict__ Cf,
                                             fp16* __restrict__ Ch,
                                             int N, int K) {
    extern __shared__ char smem[];
    const uint32_t sb = smem_u32(smem);
    const int tid  = threadIdx.x;
    const int wid  = tid >> 5, lane = tid & 31;
    const int wm   = wid >> 2, wn = wid & 3;
    const int bm   = blockIdx.y << 7;
    const int bn   = blockIdx.x << 8;
    const int T    = K >> 6;

    float acc[4][8][4] = {};

    auto load_stage = [&](int sidx, int k0) {
        uint32_t stg = sb + sidx * STAGE;
#pragma unroll
        for (int i = 0; i < 4; i++) {
            int flat = tid + i * 256;            // 0..1023: A 128 rows x 8 chunks
            int r = flat >> 3, c = flat & 7;
            CP_ASYNC16(stg + OFF_A + r * ROWB + c * 16, Aa + (size_t)(bm + r) * K + k0 + c * 8);
        }
#pragma unroll
        for (int i = 0; i < 8; i++) {
            int flat = tid + i * 256;            // 0..2047: B 256 rows x 8 chunks
            int r = flat >> 3, c = flat & 7;
            CP_ASYNC16(stg + OFF_B + r * ROWB + c * 16, Bw + (size_t)(bn + r) * K + k0 + c * 8);
        }
        CP_COMMIT();
    };

    load_stage(0, 0);
    load_stage(1, 64);
    load_stage(2, 128);

    const int aRow  = lane & 15;
    const int aKc   = (lane >> 4) * 16;
    const int bNloc = ((lane >> 4) << 3) + (lane & 7);
    const int bKc   = ((lane >> 3) & 1) * 16;

    for (int it = 0; it < T; it++) {
        int remain = T - 1 - it;
        if (remain >= 2)      { CP_WAIT2(); }
        else if (remain == 1) { CP_WAIT1(); }
        else                  { CP_WAIT0(); }
        __syncthreads();
        // safe: stage (it+3)%4 == (it-1)%4; all reads of it-1 completed before this sync
        if (it + 3 < T) load_stage((it + 3) % NSTAGE, (it + 3) << 6);

        uint32_t stg = sb + (it % NSTAGE) * STAGE;
        uint32_t aB = stg + OFF_A + (wm * 64 + aRow) * ROWB + aKc;
        uint32_t bB = stg + OFF_B + (wn * 64 + bNloc) * ROWB + bKc;

#pragma unroll
        for (int kk = 0; kk < 4; kk++) {
            uint32_t ka = kk * 32;
            uint32_t af[4][4], bf[8][2];
#pragma unroll
            for (int mi = 0; mi < 4; mi++)
                ldsm4(af[mi], aB + mi * 16 * ROWB + ka);
#pragma unroll
            for (int ni2 = 0; ni2 < 4; ni2++) {
                uint32_t r[4];
                ldsm4(r, bB + ni2 * 16 * ROWB + ka);
                bf[ni2 * 2][0] = r[0]; bf[ni2 * 2][1] = r[1];
                bf[ni2 * 2 + 1][0] = r[2]; bf[ni2 * 2 + 1][1] = r[3];
            }
#pragma unroll
            for (int mi = 0; mi < 4; mi++)
#pragma unroll
                for (int ni = 0; ni < 8; ni++)
                    mma_f16(acc[mi][ni], af[mi], bf[ni]);
        }
    }

#pragma unroll
    for (int mi = 0; mi < 4; mi++) {
        int row0 = bm + wm * 64 + mi * 16 + (lane >> 2);
#pragma unroll
        for (int ni = 0; ni < 8; ni++) {
            int col = bn + wn * 64 + ni * 8 + (lane & 3) * 2;
            float b0 = bias[col], b1 = bias[col + 1];
#pragma unroll
            for (int half = 0; half < 2; half++) {
                int row = row0 + half * 8;
                float v0 = acc[mi][ni][half * 2]     + b0;
                float v1 = acc[mi][ni][half * 2 + 1] + b1;
                if (MODE == 2) {
                    v0 = fmaxf(v0, 0.f); v1 = fmaxf(v1, 0.f);
                    *(uint32_t*)(Ch + (size_t)row * N + col) = pack_h2(v0, v1);
                } else if (MODE == 3) {
                    *(uint32_t*)(Ch + (size_t)row * N + col) = pack_h2(v0, v1);
                } else {
                    float* dst = Cf + (size_t)row * N + col;
                    float2 o; o.x = v0 + dst[0]; o.y = v1 + dst[1];
                    *(float2*)dst = o;
                }
            }
        }
    }
}

// ---------------- fused flash attention (trans-V, fused QKV input, len-skip) ----------------
// grid (SEQ/128, BATCH*NHEAD), 256 threads (8 warps x 16 q-rows)
#define FA_ROWB  144
#define FA_Q   0
#define FA_K0  18432
#define FA_K1  36864
#define FA_V0  55296
#define FA_V1  73728
#define FA_SMEM 92160

__global__ void __launch_bounds__(256) fattn(const fp16* __restrict__ QKV,
                                             const int* __restrict__ lengths,
                                             fp16* __restrict__ oh) {
    extern __shared__ char smem[];
    const uint32_t sb = smem_u32(smem);
    const int tid = threadIdx.x, w = tid >> 5, lane = tid & 31;
    const int qb = blockIdx.x, bh = blockIdx.y;
    const int b = bh >> 4, h = bh & 15;
    const int len = lengths[b];
    const int nkb = (len + 127) >> 7;
    const int tok0 = b * SEQ + qb * 128;

#pragma unroll
    for (int i = 0; i < 4; i++) {
        int flat = tid + i * 256; int r = flat >> 3, c = flat & 7;
        CP_ASYNC16(sb + FA_Q + r * FA_ROWB + c * 16,  QKV + (size_t)(tok0 + r) * QKVW + h * 64 + c * 8);
        CP_ASYNC16(sb + FA_K0 + r * FA_ROWB + c * 16, QKV + (size_t)(b * SEQ + r) * QKVW + 1024 + h * 64 + c * 8);
        CP_ASYNC16(sb + FA_V0 + r * FA_ROWB + c * 16, QKV + (size_t)(b * SEQ + r) * QKVW + 2048 + h * 64 + c * 8);
    }
    CP_COMMIT();
#pragma unroll
    for (int i = 0; i < 4; i++) {
        int flat = tid + i * 256; int r = flat >> 3, c = flat & 7;
        CP_ASYNC16(sb + FA_K1 + r * FA_ROWB + c * 16, QKV + (size_t)(b * SEQ + 128 + r) * QKVW + 1024 + h * 64 + c * 8);
        CP_ASYNC16(sb + FA_V1 + r * FA_ROWB + c * 16, QKV + (size_t)(b * SEQ + 128 + r) * QKVW + 2048 + h * 64 + c * 8);
    }
    CP_COMMIT();

    const int bNloc = ((lane >> 4) << 3) + (lane & 7);
    const int bKc   = ((lane >> 3) & 1) * 16;
    const int vg = lane >> 3, vi = lane & 7;
    const uint32_t vOff = (uint32_t)(((vg & 1) * 8 + vi) * FA_ROWB + (vg >> 1) * 16);

    uint32_t qf[4][4];
    float O[8][4] = {};
    float m0 = -1e30f, m1 = -1e30f, l0 = 0.f, l1 = 0.f;

    for (int kb = 0; kb < nkb; kb++) {
        if (kb < nkb - 1) { CP_WAIT1(); } else { CP_WAIT0(); }
        __syncthreads();

        if (kb == 0) {
            uint32_t qa = sb + FA_Q + (w * 16 + (lane & 15)) * FA_ROWB + (lane >> 4) * 16;
#pragma unroll
            for (int kc = 0; kc < 4; kc++) ldsm4(qf[kc], qa + kc * 32);
        }

        // ---- QK^T ----
        uint32_t koff = sb + ((kb & 1) ? FA_K1 : FA_K0);
        float p[16][4];
#pragma unroll
        for (int nt16 = 0; nt16 < 8; nt16++) {
            float s0[4] = {}, s1[4] = {};
#pragma unroll
            for (int kc = 0; kc < 4; kc++) {
                uint32_t r4[4];
                ldsm4(r4, koff + (nt16 * 16 + bNloc) * FA_ROWB + bKc + kc * 32);
                uint32_t bb0[2] = { r4[0], r4[1] }, bb1[2] = { r4[2], r4[3] };
                mma_f16(s0, qf[kc], bb0);
                mma_f16(s1, qf[kc], bb1);
            }
#pragma unroll
            for (int j = 0; j < 4; j++) { p[nt16 * 2][j] = s0[j]; p[nt16 * 2 + 1][j] = s1[j]; }
        }

        // ---- mask + online softmax ----
        float mx0 = -1e30f, mx1 = -1e30f;
#pragma unroll
        for (int nt = 0; nt < 16; nt++) {
            int c = kb * 128 + nt * 8 + (lane & 3) * 2;
            float s0 = p[nt][0] * 0.125f, s1 = p[nt][1] * 0.125f;
            float s2 = p[nt][2] * 0.125f, s3 = p[nt][3] * 0.125f;
            if (c     >= len) { s0 = -1e30f; s2 = -1e30f; }
            if (c + 1 >= len) { s1 = -1e30f; s3 = -1e30f; }
            p[nt][0] = s0; p[nt][1] = s1; p[nt][2] = s2; p[nt][3] = s3;
            mx0 = fmaxf(mx0, fmaxf(s0, s1));
            mx1 = fmaxf(mx1, fmaxf(s2, s3));
        }
        mx0 = fmaxf(mx0, __shfl_xor_sync(0xffffffffu, mx0, 1));
        mx0 = fmaxf(mx0, __shfl_xor_sync(0xffffffffu, mx0, 2));
        mx1 = fmaxf(mx1, __shfl_xor_sync(0xffffffffu, mx1, 1));
        mx1 = fmaxf(mx1, __shfl_xor_sync(0xffffffffu, mx1, 2));
        float mn0 = fmaxf(m0, mx0), mn1 = fmaxf(m1, mx1);
        float corr0 = __expf(m0 - mn0), corr1 = __expf(m1 - mn1);
        m0 = mn0; m1 = mn1;
        float ls0 = 0.f, ls1 = 0.f;
#pragma unroll
        for (int nt = 0; nt < 16; nt++) {
            float e0 = __expf(p[nt][0] - mn0), e1 = __expf(p[nt][1] - mn0);
            float e2 = __expf(p[nt][2] - mn1), e3 = __expf(p[nt][3] - mn1);
            p[nt][0] = e0; p[nt][1] = e1; p[nt][2] = e2; p[nt][3] = e3;
            ls0 += e0 + e1; ls1 += e2 + e3;
        }
        l0 = l0 * corr0 + ls0;
        l1 = l1 * corr1 + ls1;
#pragma unroll
        for (int ni = 0; ni < 8; ni++) {
            O[ni][0] *= corr0; O[ni][1] *= corr0;
            O[ni][2] *= corr1; O[ni][3] *= corr1;
        }

        // ---- P @ V ----
        uint32_t vbase = sb + ((kb & 1) ? FA_V1 : FA_V0) + vOff;
#pragma unroll
        for (int kc = 0; kc < 8; kc++) {
            uint32_t pf[4];
            pf[0] = pack_h2(p[2 * kc][0],     p[2 * kc][1]);
            pf[1] = pack_h2(p[2 * kc][2],     p[2 * kc][3]);
            pf[2] = pack_h2(p[2 * kc + 1][0], p[2 * kc + 1][1]);
            pf[3] = pack_h2(p[2 * kc + 1][2], p[2 * kc + 1][3]);
#pragma unroll
            for (int nt16 = 0; nt16 < 4; nt16++) {
                uint32_t r4[4];
                ldsm4t(r4, vbase + kc * 16 * FA_ROWB + nt16 * 32);
                uint32_t bb0[2] = { r4[0], r4[1] }, bb1[2] = { r4[2], r4[3] };
                mma_f16(O[nt16 * 2], pf, bb0);
                mma_f16(O[nt16 * 2 + 1], pf, bb1);
            }
        }

        __syncthreads();
        if (kb + 2 < nkb) {
            int blk = kb + 2;
            uint32_t kd = sb + ((blk & 1) ? FA_K1 : FA_K0);
            uint32_t vd = sb + ((blk & 1) ? FA_V1 : FA_V0);
#pragma unroll
            for (int i = 0; i < 4; i++) {
                int flat = tid + i * 256; int r = flat >> 3, c = flat & 7;
                CP_ASYNC16(kd + r * FA_ROWB + c * 16, QKV + (size_t)(b * SEQ + blk * 128 + r) * QKVW + 1024 + h * 64 + c * 8);
                CP_ASYNC16(vd + r * FA_ROWB + c * 16, QKV + (size_t)(b * SEQ + blk * 128 + r) * QKVW + 2048 + h * 64 + c * 8);
            }
            CP_COMMIT();
        }
    }

    l0 += __shfl_xor_sync(0xffffffffu, l0, 1);
    l0 += __shfl_xor_sync(0xffffffffu, l0, 2);
    l1 += __shfl_xor_sync(0xffffffffu, l1, 1);
    l1 += __shfl_xor_sync(0xffffffffu, l1, 2);
    float inv0 = 1.f / l0, inv1 = 1.f / l1;
    int row0 = tok0 + w * 16 + (lane >> 2);
    int row1 = row0 + 8;
#pragma unroll
    for (int nt = 0; nt < 8; nt++) {
        int col = h * 64 + nt * 8 + (lane & 3) * 2;
        *(uint32_t*)(oh + (size_t)row0 * DMODEL + col) = pack_h2(O[nt][0] * inv0, O[nt][1] * inv0);
        *(uint32_t*)(oh + (size_t)row1 * DMODEL + col) = pack_h2(O[nt][2] * inv1, O[nt][3] * inv1);
    }
}

// ---------------- weight transpose to fp16 (half2-vectorized stores) ----------------
__global__ void wsplit(const float* __restrict__ W, fp16* __restrict__ Tw,
                       int K, int N, int ldRows, int roff) {
    __shared__ float t[32][33];
    const float* Wl = W + (size_t)blockIdx.z * K * N;
    fp16* tw = Tw + (size_t)blockIdx.z * K * ldRows;
    int k0 = blockIdx.y << 5, n0 = blockIdx.x << 5;
    int tx = threadIdx.x, ty = threadIdx.y;
    int tid = ty * 32 + tx;
#pragma unroll
    for (int i = 0; i < 4; i++)
        t[ty + i * 8][tx] = Wl[(size_t)(k0 + ty + i * 8) * N + n0 + tx];
    __syncthreads();
#pragma unroll
    for (int it = 0; it < 2; it++) {
        int idx = tid + it * 256;
        int n   = idx >> 4;
        int kp  = idx & 15;
        float v0 = t[2 * kp][n];
        float v1 = t[2 * kp + 1][n];
        *(uint32_t*)(tw + (size_t)(roff + n0 + n) * K + k0 + 2 * kp) = pack_h2(v0, v1);
    }
}

// ---------------- concat QKV bias ----------------
__global__ void bcat(const float* __restrict__ bq, const float* __restrict__ bkv,
                     float* __restrict__ bqkv) {
    int idx = blockIdx.x * 256 + threadIdx.x;
    if (idx >= NLAYER * QKVW) return;
    int l = idx / QKVW, j = idx % QKVW;
    bqkv[idx] = (j < DMODEL) ? bq[l * DMODEL + j] : bkv[l * KVW + j - DMODEL];
}

// ---------------- positional encoding ----------------
__global__ void pe_kernel(float* __restrict__ pe) {
    int idx = blockIdx.x * 256 + threadIdx.x;
    if (idx >= SEQ * DMODEL) return;
    int s = idx >> 10;
    int d = idx & 1023;
    double e = (double)(2 * (d >> 1)) / 1024.0;
    double ang = (double)s * exp(-e * log(10000.0));
    pe[idx] = (d & 1) ? (float)cos(ang) : (float)sin(ang);
}

// ---------------- embedding + PE ----------------
__global__ void embed_kernel(const int* __restrict__ tokens, const float* __restrict__ emb,
                             const float* __restrict__ pe, float* __restrict__ x) {
    int idx = blockIdx.x * 256 + threadIdx.x;
    if (idx >= NTOK * DMODEL) return;
    int row = idx >> 10;
    int d = idx & 1023;
    int s = row & (SEQ - 1);
    x[idx] = emb[(size_t)tokens[row] * DMODEL + d] * 32.0f + pe[(s << 10) + d];
}

// ---------------- layernorm, warp-per-row (HALF=1 -> fp16 out; 0 -> fp32) ----------------
template <int HALF>
__global__ void __launch_bounds__(256) ln_kernel(const float* __restrict__ in,
                                                 const float* __restrict__ g,
                                                 const float* __restrict__ b,
                                                 float* __restrict__ outf,
                                                 fp16* __restrict__ oh) {
    int row = blockIdx.x * 8 + (threadIdx.x >> 5);
    int lane = threadIdx.x & 31;
    const float* xr = in + (size_t)row * DMODEL;
    float4 v[8];
    float s = 0.f, s2 = 0.f;
#pragma unroll
    for (int i = 0; i < 8; i++) {
        v[i] = *(const float4*)(xr + lane * 4 + i * 128);
        s  += v[i].x + v[i].y + v[i].z + v[i].w;
        s2 += v[i].x * v[i].x + v[i].y * v[i].y + v[i].z * v[i].z + v[i].w * v[i].w;
    }
#pragma unroll
    for (int off = 16; off; off >>= 1) {
        s  += __shfl_xor_sync(0xffffffffu, s, off);
        s2 += __shfl_xor_sync(0xffffffffu, s2, off);
    }
    float m = s * (1.f / DMODEL);
    float var = s2 * (1.f / DMODEL) - m * m;
    float rstd = rsqrtf(var + 1e-5f);
#pragma unroll
    for (int i = 0; i < 8; i++) {
        int c = lane * 4 + i * 128;
        float4 gv = *(const float4*)(g + c);
        float4 bv = *(const float4*)(b + c);
        float o0 = (v[i].x - m) * rstd * gv.x + bv.x;
        float o1 = (v[i].y - m) * rstd * gv.y + bv.y;
        float o2 = (v[i].z - m) * rstd * gv.z + bv.z;
        float o3 = (v[i].w - m) * rstd * gv.w + bv.w;
        if (HALF) {
            uint2 pk;
            pk.x = pack_h2(o0, o1);
            pk.y = pack_h2(o2, o3);
            *(uint2*)(oh + (size_t)row * DMODEL + c) = pk;
        } else {
            float4 o; o.x = o0; o.y = o1; o.z = o2; o.w = o3;
            *(float4*)(outf + (size_t)row * DMODEL + c) = o;
        }
    }
}

// ---------------- host ----------------
extern "C" void kernel_launch(void* const* d_in, const int* in_sizes, int n_in,
                              void* d_out, int out_size) {
    const int*   tokens = (const int*)  d_in[0];
    const int*   lengths= (const int*)  d_in[1];
    const float* emb    = (const float*)d_in[2];
    const float* Wq     = (const float*)d_in[3];
    const float* bq     = (const float*)d_in[4];
    const float* Wkv    = (const float*)d_in[5];
    const float* bkv    = (const float*)d_in[6];
    const float* Wo     = (const float*)d_in[7];
    const float* bo     = (const float*)d_in[8];
    const float* lag    = (const float*)d_in[9];
    const float* lab    = (const float*)d_in[10];
    const float* W1     = (const float*)d_in[11];
    const float* b1     = (const float*)d_in[12];
    const float* W2     = (const float*)d_in[13];
    const float* b2     = (const float*)d_in[14];
    const float* lfg    = (const float*)d_in[15];
    const float* lfb    = (const float*)d_in[16];
    const float* lng    = (const float*)d_in[17];
    const float* lnb    = (const float*)d_in[18];

    float *x, *pe, *bqkv;
    fp16 *qkv16, *h16, *o16, *f16;
    fp16 *wqkvT, *woT, *w1T, *w2T;
    cudaGetSymbolAddress((void**)&x, g_x);
    cudaGetSymbolAddress((void**)&pe, g_pe);
    cudaGetSymbolAddress((void**)&qkv16, g_qkv16);
    cudaGetSymbolAddress((void**)&h16, g_h16);
    cudaGetSymbolAddress((void**)&o16, g_o16);
    cudaGetSymbolAddress((void**)&f16, g_f16);
    cudaGetSymbolAddress((void**)&wqkvT, g_wqkvT);
    cudaGetSymbolAddress((void**)&woT, g_woT);
    cudaGetSymbolAddress((void**)&w1T, g_w1T);
    cudaGetSymbolAddress((void**)&w2T, g_w2T);
    cudaGetSymbolAddress((void**)&bqkv, g_bqkv);

    cudaFuncSetAttribute(tgemm<1>, cudaFuncAttributeMaxDynamicSharedMemorySize, SMEM_T);
    cudaFuncSetAttribute(tgemm<2>, cudaFuncAttributeMaxDynamicSharedMemorySize, SMEM_T);
    cudaFuncSetAttribute(tgemm<3>, cudaFuncAttributeMaxDynamicSharedMemorySize, SMEM_T);
    cudaFuncSetAttribute(fattn, cudaFuncAttributeMaxDynamicSharedMemorySize, FA_SMEM);

    dim3 tb(32, 8);
    wsplit<<<dim3(DMODEL / 32, DMODEL / 32, NLAYER), tb>>>(Wq,  wqkvT, DMODEL, DMODEL, QKVW, 0);
    wsplit<<<dim3(KVW / 32,    DMODEL / 32, NLAYER), tb>>>(Wkv, wqkvT, DMODEL, KVW,   QKVW, DMODEL);
    wsplit<<<dim3(DMODEL / 32, DMODEL / 32, NLAYER), tb>>>(Wo,  woT,   DMODEL, DMODEL, DMODEL, 0);
    wsplit<<<dim3(DFF / 32,    DMODEL / 32, NLAYER), tb>>>(W1,  w1T,   DMODEL, DFF,   DFF, 0);
    wsplit<<<dim3(DMODEL / 32, DFF / 32,    NLAYER), tb>>>(W2,  w2T,   DFF,    DMODEL, DMODEL, 0);
    bcat<<<(NLAYER * QKVW + 255) / 256, 256>>>(bq, bkv, bqkv);

    pe_kernel<<<(SEQ * DMODEL) / 256, 256>>>(pe);
    embed_kernel<<<(NTOK * DMODEL) / 256, 256>>>(tokens, emb, pe, x);

    for (int l = 0; l < NLAYER; l++) {
        size_t oQKV = (size_t)l * DMODEL * QKVW;
        size_t oO   = (size_t)l * DMODEL * DMODEL;
        size_t o1w  = (size_t)l * DMODEL * DFF;

        // attention sublayer
        ln_kernel<1><<<NTOK / 8, 256>>>(x, lag + l * DMODEL, lab + l * DMODEL, nullptr, h16);
        tgemm<3><<<dim3(QKVW / 256, NTOK / 128), 256, SMEM_T>>>(
            h16, wqkvT + oQKV, bqkv + l * QKVW, nullptr, qkv16, QKVW, DMODEL);
        fattn<<<dim3(SEQ / 128, BATCH * NHEAD), 256, FA_SMEM>>>(qkv16, lengths, o16);
        tgemm<1><<<dim3(DMODEL / 256, NTOK / 128), 256, SMEM_T>>>(
            o16, woT + oO, bo + l * DMODEL, x, nullptr, DMODEL, DMODEL);

        // FFN sublayer
        ln_kernel<1><<<NTOK / 8, 256>>>(x, lfg + l * DMODEL, lfb + l * DMODEL, nullptr, h16);
        tgemm<2><<<dim3(DFF / 256, NTOK / 128), 256, SMEM_T>>>(
            h16, w1T + o1w, b1 + l * DFF, nullptr, f16, DFF, DMODEL);
        tgemm<1><<<dim3(DMODEL / 256, NTOK / 128), 256, SMEM_T>>>(
            f16, w2T + o1w, b2 + l * DMODEL, x, nullptr, DMODEL, DFF);
    }

    ln_kernel<0><<<NTOK / 8, 256>>>(x, lng, lnb, (float*)d_out, nullptr);
}

// round 17
// speedup vs baseline: 1.7309x; 1.7309x over previous
#include <cuda_runtime.h>
#include <cuda_fp16.h>
#include <math.h>
#include <stdint.h>

// ---------------- problem dims ----------------
#define BATCH   8
#define SEQ     512
#define NTOK    4096
#define DMODEL  1024
#define NHEAD   16
#define DHEAD   64
#define DFF     4096
#define NLAYER  6
#define KVW     2048
#define QKVW    3072

typedef __half fp16;

// ---------------- scratch ----------------
__device__ float g_x [(size_t)NTOK * DMODEL];
__device__ float g_pe[(size_t)SEQ * DMODEL];

__device__ fp16 g_qkv16[(size_t)NTOK * QKVW];
__device__ fp16 g_h16[(size_t)NTOK * DMODEL];
__device__ fp16 g_o16[(size_t)NTOK * DMODEL];
__device__ fp16 g_f16[(size_t)NTOK * DFF];

// transposed weights: [N,K] fp16
__device__ fp16 g_wqkvT[(size_t)NLAYER * DMODEL * QKVW];
__device__ fp16 g_woT [(size_t)NLAYER * DMODEL * DMODEL];
__device__ fp16 g_w1T [(size_t)NLAYER * DMODEL * DFF];
__device__ fp16 g_w2T [(size_t)NLAYER * DFF * DMODEL];
__device__ float g_bqkv[(size_t)NLAYER * QKVW];

// ---------------- helpers ----------------
__device__ __forceinline__ uint32_t smem_u32(const void* p) {
    uint32_t a;
    asm("{ .reg .u64 t; cvta.to.shared.u64 t, %1; cvt.u32.u64 %0, t; }" : "=r"(a) : "l"(p));
    return a;
}
#define CP_ASYNC16(dst, src) \
    asm volatile("cp.async.cg.shared.global [%0], [%1], 16;" :: "r"(dst), "l"(src) : "memory")
#define CP_COMMIT() asm volatile("cp.async.commit_group;" ::: "memory")
#define CP_WAIT1()  asm volatile("cp.async.wait_group 1;" ::: "memory")
#define CP_WAIT0()  asm volatile("cp.async.wait_group 0;" ::: "memory")

__device__ __forceinline__ void ldsm4(uint32_t* r, uint32_t addr) {
    asm volatile("ldmatrix.sync.aligned.m8n8.x4.shared.b16 {%0,%1,%2,%3}, [%4];"
        : "=r"(r[0]), "=r"(r[1]), "=r"(r[2]), "=r"(r[3]) : "r"(addr));
}
__device__ __forceinline__ void ldsm4t(uint32_t* r, uint32_t addr) {
    asm volatile("ldmatrix.sync.aligned.m8n8.x4.trans.shared.b16 {%0,%1,%2,%3}, [%4];"
        : "=r"(r[0]), "=r"(r[1]), "=r"(r[2]), "=r"(r[3]) : "r"(addr));
}
__device__ __forceinline__ void mma_f16(float* d, const uint32_t* a, const uint32_t* b) {
    asm volatile("mma.sync.aligned.m16n8k16.row.col.f32.f16.f16.f32 "
        "{%0,%1,%2,%3}, {%4,%5,%6,%7}, {%8,%9}, {%0,%1,%2,%3};"
        : "+f"(d[0]), "+f"(d[1]), "+f"(d[2]), "+f"(d[3])
        : "r"(a[0]), "r"(a[1]), "r"(a[2]), "r"(a[3]), "r"(b[0]), "r"(b[1]));
}
__device__ __forceinline__ uint32_t pack_h2(float a, float b) {
    __half2 h = __halves2half2(__float2half_rn(a), __float2half_rn(b));
    return *(uint32_t*)&h;
}

// ---------------- fp16 1-pass GEMM: C[M,N] = A @ Bt^T ----------------
// CTA 128x256, 8 warps (2x4), warp tile 64x64, BK=64, 3-stage cp.async,
// ONE barrier per iteration (loads issued post-sync; stage (it+2)%3==(it-1)%3 drained).
// MODE 1: fp32 +residual+bias; 2: relu -> fp16; 3: fp16
#define ROWB   144
#define OFF_A  0
#define OFF_B  18432
#define STAGE  55296
#define NSTAGE 3
#define SMEM_T (NSTAGE * STAGE)

template <int MODE>
__global__ void __launch_bounds__(256) tgemm(const fp16* __restrict__ Aa,
                                             const fp16* __restrict__ Bw,
                                             const float* __restrict__ bias,
                                             float* __restrict__ Cf,
                                             fp16* __restrict__ Ch,
                                             int N, int K) {
    extern __shared__ char smem[];
    const uint32_t sb = smem_u32(smem);
    const int tid  = threadIdx.x;
    const int wid  = tid >> 5, lane = tid & 31;
    const int wm   = wid >> 2, wn = wid & 3;
    const int bm   = blockIdx.y << 7;
    const int bn   = blockIdx.x << 8;
    const int T    = K >> 6;

    float acc[4][8][4] = {};

    auto load_stage = [&](int sidx, int k0) {
        uint32_t stg = sb + sidx * STAGE;
#pragma unroll
        for (int i = 0; i < 4; i++) {
            int flat = tid + i * 256;            // 0..1023: A 128 rows x 8 chunks
            int r = flat >> 3, c = flat & 7;
            CP_ASYNC16(stg + OFF_A + r * ROWB + c * 16, Aa + (size_t)(bm + r) * K + k0 + c * 8);
        }
#pragma unroll
        for (int i = 0; i < 8; i++) {
            int flat = tid + i * 256;            // 0..2047: B 256 rows x 8 chunks
            int r = flat >> 3, c = flat & 7;
            CP_ASYNC16(stg + OFF_B + r * ROWB + c * 16, Bw + (size_t)(bn + r) * K + k0 + c * 8);
        }
        CP_COMMIT();
    };

    load_stage(0, 0);
    load_stage(1, 64);

    const int aRow  = lane & 15;
    const int aKc   = (lane >> 4) * 16;
    const int bNloc = ((lane >> 4) << 3) + (lane & 7);
    const int bKc   = ((lane >> 3) & 1) * 16;

    for (int it = 0; it < T; it++) {
        if (it < T - 1) { CP_WAIT1(); } else { CP_WAIT0(); }
        __syncthreads();
        // safe: stage (it+2)%3 == (it-1)%3; all reads of it-1 completed before this sync
        if (it + 2 < T) load_stage((it + 2) % NSTAGE, (it + 2) << 6);

        uint32_t stg = sb + (it % NSTAGE) * STAGE;
        uint32_t aB = stg + OFF_A + (wm * 64 + aRow) * ROWB + aKc;
        uint32_t bB = stg + OFF_B + (wn * 64 + bNloc) * ROWB + bKc;

#pragma unroll
        for (int kk = 0; kk < 4; kk++) {
            uint32_t ka = kk * 32;
            uint32_t af[4][4], bf[8][2];
#pragma unroll
            for (int mi = 0; mi < 4; mi++)
                ldsm4(af[mi], aB + mi * 16 * ROWB + ka);
#pragma unroll
            for (int ni2 = 0; ni2 < 4; ni2++) {
                uint32_t r[4];
                ldsm4(r, bB + ni2 * 16 * ROWB + ka);
                bf[ni2 * 2][0] = r[0]; bf[ni2 * 2][1] = r[1];
                bf[ni2 * 2 + 1][0] = r[2]; bf[ni2 * 2 + 1][1] = r[3];
            }
#pragma unroll
            for (int mi = 0; mi < 4; mi++)
#pragma unroll
                for (int ni = 0; ni < 8; ni++)
                    mma_f16(acc[mi][ni], af[mi], bf[ni]);
        }
    }

#pragma unroll
    for (int mi = 0; mi < 4; mi++) {
        int row0 = bm + wm * 64 + mi * 16 + (lane >> 2);
#pragma unroll
        for (int ni = 0; ni < 8; ni++) {
            int col = bn + wn * 64 + ni * 8 + (lane & 3) * 2;
            float b0 = bias[col], b1 = bias[col + 1];
#pragma unroll
            for (int half = 0; half < 2; half++) {
                int row = row0 + half * 8;
                float v0 = acc[mi][ni][half * 2]     + b0;
                float v1 = acc[mi][ni][half * 2 + 1] + b1;
                if (MODE == 2) {
                    v0 = fmaxf(v0, 0.f); v1 = fmaxf(v1, 0.f);
                    *(uint32_t*)(Ch + (size_t)row * N + col) = pack_h2(v0, v1);
                } else if (MODE == 3) {
                    *(uint32_t*)(Ch + (size_t)row * N + col) = pack_h2(v0, v1);
                } else {
                    float* dst = Cf + (size_t)row * N + col;
                    float2 o; o.x = v0 + dst[0]; o.y = v1 + dst[1];
                    *(float2*)dst = o;
                }
            }
        }
    }
}

// ---------------- fused flash attention (trans-V, fused QKV input, len-skip) ----------------
// grid (SEQ/128, BATCH*NHEAD), 256 threads (8 warps x 16 q-rows)
#define FA_ROWB  144
#define FA_Q   0
#define FA_K0  18432
#define FA_K1  36864
#define FA_V0  55296
#define FA_V1  73728
#define FA_SMEM 92160

__global__ void __launch_bounds__(256) fattn(const fp16* __restrict__ QKV,
                                             const int* __restrict__ lengths,
                                             fp16* __restrict__ oh) {
    extern __shared__ char smem[];
    const uint32_t sb = smem_u32(smem);
    const int tid = threadIdx.x, w = tid >> 5, lane = tid & 31;
    const int qb = blockIdx.x, bh = blockIdx.y;
    const int b = bh >> 4, h = bh & 15;
    const int len = lengths[b];
    const int nkb = (len + 127) >> 7;
    const int tok0 = b * SEQ + qb * 128;

#pragma unroll
    for (int i = 0; i < 4; i++) {
        int flat = tid + i * 256; int r = flat >> 3, c = flat & 7;
        CP_ASYNC16(sb + FA_Q + r * FA_ROWB + c * 16,  QKV + (size_t)(tok0 + r) * QKVW + h * 64 + c * 8);
        CP_ASYNC16(sb + FA_K0 + r * FA_ROWB + c * 16, QKV + (size_t)(b * SEQ + r) * QKVW + 1024 + h * 64 + c * 8);
        CP_ASYNC16(sb + FA_V0 + r * FA_ROWB + c * 16, QKV + (size_t)(b * SEQ + r) * QKVW + 2048 + h * 64 + c * 8);
    }
    CP_COMMIT();
#pragma unroll
    for (int i = 0; i < 4; i++) {
        int flat = tid + i * 256; int r = flat >> 3, c = flat & 7;
        CP_ASYNC16(sb + FA_K1 + r * FA_ROWB + c * 16, QKV + (size_t)(b * SEQ + 128 + r) * QKVW + 1024 + h * 64 + c * 8);
        CP_ASYNC16(sb + FA_V1 + r * FA_ROWB + c * 16, QKV + (size_t)(b * SEQ + 128 + r) * QKVW + 2048 + h * 64 + c * 8);
    }
    CP_COMMIT();

    const int bNloc = ((lane >> 4) << 3) + (lane & 7);
    const int bKc   = ((lane >> 3) & 1) * 16;
    const int vg = lane >> 3, vi = lane & 7;
    const uint32_t vOff = (uint32_t)(((vg & 1) * 8 + vi) * FA_ROWB + (vg >> 1) * 16);

    uint32_t qf[4][4];
    float O[8][4] = {};
    float m0 = -1e30f, m1 = -1e30f, l0 = 0.f, l1 = 0.f;

    for (int kb = 0; kb < nkb; kb++) {
        if (kb < nkb - 1) { CP_WAIT1(); } else { CP_WAIT0(); }
        __syncthreads();

        if (kb == 0) {
            uint32_t qa = sb + FA_Q + (w * 16 + (lane & 15)) * FA_ROWB + (lane >> 4) * 16;
#pragma unroll
            for (int kc = 0; kc < 4; kc++) ldsm4(qf[kc], qa + kc * 32);
        }

        // ---- QK^T ----
        uint32_t koff = sb + ((kb & 1) ? FA_K1 : FA_K0);
        float p[16][4];
#pragma unroll
        for (int nt16 = 0; nt16 < 8; nt16++) {
            float s0[4] = {}, s1[4] = {};
#pragma unroll
            for (int kc = 0; kc < 4; kc++) {
                uint32_t r4[4];
                ldsm4(r4, koff + (nt16 * 16 + bNloc) * FA_ROWB + bKc + kc * 32);
                uint32_t bb0[2] = { r4[0], r4[1] }, bb1[2] = { r4[2], r4[3] };
                mma_f16(s0, qf[kc], bb0);
                mma_f16(s1, qf[kc], bb1);
            }
#pragma unroll
            for (int j = 0; j < 4; j++) { p[nt16 * 2][j] = s0[j]; p[nt16 * 2 + 1][j] = s1[j]; }
        }

        // ---- mask + online softmax ----
        float mx0 = -1e30f, mx1 = -1e30f;
#pragma unroll
        for (int nt = 0; nt < 16; nt++) {
            int c = kb * 128 + nt * 8 + (lane & 3) * 2;
            float s0 = p[nt][0] * 0.125f, s1 = p[nt][1] * 0.125f;
            float s2 = p[nt][2] * 0.125f, s3 = p[nt][3] * 0.125f;
            if (c     >= len) { s0 = -1e30f; s2 = -1e30f; }
            if (c + 1 >= len) { s1 = -1e30f; s3 = -1e30f; }
            p[nt][0] = s0; p[nt][1] = s1; p[nt][2] = s2; p[nt][3] = s3;
            mx0 = fmaxf(mx0, fmaxf(s0, s1));
            mx1 = fmaxf(mx1, fmaxf(s2, s3));
        }
        mx0 = fmaxf(mx0, __shfl_xor_sync(0xffffffffu, mx0, 1));
        mx0 = fmaxf(mx0, __shfl_xor_sync(0xffffffffu, mx0, 2));
        mx1 = fmaxf(mx1, __shfl_xor_sync(0xffffffffu, mx1, 1));
        mx1 = fmaxf(mx1, __shfl_xor_sync(0xffffffffu, mx1, 2));
        float mn0 = fmaxf(m0, mx0), mn1 = fmaxf(m1, mx1);
        float corr0 = __expf(m0 - mn0), corr1 = __expf(m1 - mn1);
        m0 = mn0; m1 = mn1;
        float ls0 = 0.f, ls1 = 0.f;
#pragma unroll
        for (int nt = 0; nt < 16; nt++) {
            float e0 = __expf(p[nt][0] - mn0), e1 = __expf(p[nt][1] - mn0);
            float e2 = __expf(p[nt][2] - mn1), e3 = __expf(p[nt][3] - mn1);
            p[nt][0] = e0; p[nt][1] = e1; p[nt][2] = e2; p[nt][3] = e3;
            ls0 += e0 + e1; ls1 += e2 + e3;
        }
        l0 = l0 * corr0 + ls0;
        l1 = l1 * corr1 + ls1;
#pragma unroll
        for (int ni = 0; ni < 8; ni++) {
            O[ni][0] *= corr0; O[ni][1] *= corr0;
            O[ni][2] *= corr1; O[ni][3] *= corr1;
        }

        // ---- P @ V ----
        uint32_t vbase = sb + ((kb & 1) ? FA_V1 : FA_V0) + vOff;
#pragma unroll
        for (int kc = 0; kc < 8; kc++) {
            uint32_t pf[4];
            pf[0] = pack_h2(p[2 * kc][0],     p[2 * kc][1]);
            pf[1] = pack_h2(p[2 * kc][2],     p[2 * kc][3]);
            pf[2] = pack_h2(p[2 * kc + 1][0], p[2 * kc + 1][1]);
            pf[3] = pack_h2(p[2 * kc + 1][2], p[2 * kc + 1][3]);
#pragma unroll
            for (int nt16 = 0; nt16 < 4; nt16++) {
                uint32_t r4[4];
                ldsm4t(r4, vbase + kc * 16 * FA_ROWB + nt16 * 32);
                uint32_t bb0[2] = { r4[0], r4[1] }, bb1[2] = { r4[2], r4[3] };
                mma_f16(O[nt16 * 2], pf, bb0);
                mma_f16(O[nt16 * 2 + 1], pf, bb1);
            }
        }

        __syncthreads();
        if (kb + 2 < nkb) {
            int blk = kb + 2;
            uint32_t kd = sb + ((blk & 1) ? FA_K1 : FA_K0);
            uint32_t vd = sb + ((blk & 1) ? FA_V1 : FA_V0);
#pragma unroll
            for (int i = 0; i < 4; i++) {
                int flat = tid + i * 256; int r = flat >> 3, c = flat & 7;
                CP_ASYNC16(kd + r * FA_ROWB + c * 16, QKV + (size_t)(b * SEQ + blk * 128 + r) * QKVW + 1024 + h * 64 + c * 8);
                CP_ASYNC16(vd + r * FA_ROWB + c * 16, QKV + (size_t)(b * SEQ + blk * 128 + r) * QKVW + 2048 + h * 64 + c * 8);
            }
            CP_COMMIT();
        }
    }

    l0 += __shfl_xor_sync(0xffffffffu, l0, 1);
    l0 += __shfl_xor_sync(0xffffffffu, l0, 2);
    l1 += __shfl_xor_sync(0xffffffffu, l1, 1);
    l1 += __shfl_xor_sync(0xffffffffu, l1, 2);
    float inv0 = 1.f / l0, inv1 = 1.f / l1;
    int row0 = tok0 + w * 16 + (lane >> 2);
    int row1 = row0 + 8;
#pragma unroll
    for (int nt = 0; nt < 8; nt++) {
        int col = h * 64 + nt * 8 + (lane & 3) * 2;
        *(uint32_t*)(oh + (size_t)row0 * DMODEL + col) = pack_h2(O[nt][0] * inv0, O[nt][1] * inv0);
        *(uint32_t*)(oh + (size_t)row1 * DMODEL + col) = pack_h2(O[nt][2] * inv1, O[nt][3] * inv1);
    }
}

// ---------------- weight transpose to fp16 (half2-vectorized stores) ----------------
__global__ void wsplit(const float* __restrict__ W, fp16* __restrict__ Tw,
                       int K, int N, int ldRows, int roff) {
    __shared__ float t[32][33];
    const float* Wl = W + (size_t)blockIdx.z * K * N;
    fp16* tw = Tw + (size_t)blockIdx.z * K * ldRows;
    int k0 = blockIdx.y << 5, n0 = blockIdx.x << 5;
    int tx = threadIdx.x, ty = threadIdx.y;
    int tid = ty * 32 + tx;
#pragma unroll
    for (int i = 0; i < 4; i++)
        t[ty + i * 8][tx] = Wl[(size_t)(k0 + ty + i * 8) * N + n0 + tx];
    __syncthreads();
#pragma unroll
    for (int it = 0; it < 2; it++) {
        int idx = tid + it * 256;
        int n   = idx >> 4;
        int kp  = idx & 15;
        float v0 = t[2 * kp][n];
        float v1 = t[2 * kp + 1][n];
        *(uint32_t*)(tw + (size_t)(roff + n0 + n) * K + k0 + 2 * kp) = pack_h2(v0, v1);
    }
}

// ---------------- concat QKV bias ----------------
__global__ void bcat(const float* __restrict__ bq, const float* __restrict__ bkv,
                     float* __restrict__ bqkv) {
    int idx = blockIdx.x * 256 + threadIdx.x;
    if (idx >= NLAYER * QKVW) return;
    int l = idx / QKVW, j = idx % QKVW;
    bqkv[idx] = (j < DMODEL) ? bq[l * DMODEL + j] : bkv[l * KVW + j - DMODEL];
}

// ---------------- positional encoding ----------------
__global__ void pe_kernel(float* __restrict__ pe) {
    int idx = blockIdx.x * 256 + threadIdx.x;
    if (idx >= SEQ * DMODEL) return;
    int s = idx >> 10;
    int d = idx & 1023;
    double e = (double)(2 * (d >> 1)) / 1024.0;
    double ang = (double)s * exp(-e * log(10000.0));
    pe[idx] = (d & 1) ? (float)cos(ang) : (float)sin(ang);
}

// ---------------- embedding + PE ----------------
__global__ void embed_kernel(const int* __restrict__ tokens, const float* __restrict__ emb,
                             const float* __restrict__ pe, float* __restrict__ x) {
    int idx = blockIdx.x * 256 + threadIdx.x;
    if (idx >= NTOK * DMODEL) return;
    int row = idx >> 10;
    int d = idx & 1023;
    int s = row & (SEQ - 1);
    x[idx] = emb[(size_t)tokens[row] * DMODEL + d] * 32.0f + pe[(s << 10) + d];
}

// ---------------- layernorm, warp-per-row (HALF=1 -> fp16 out; 0 -> fp32) ----------------
template <int HALF>
__global__ void __launch_bounds__(256) ln_kernel(const float* __restrict__ in,
                                                 const float* __restrict__ g,
                                                 const float* __restrict__ b,
                                                 float* __restrict__ outf,
                                                 fp16* __restrict__ oh) {
    int row = blockIdx.x * 8 + (threadIdx.x >> 5);
    int lane = threadIdx.x & 31;
    const float* xr = in + (size_t)row * DMODEL;
    float4 v[8];
    float s = 0.f, s2 = 0.f;
#pragma unroll
    for (int i = 0; i < 8; i++) {
        v[i] = *(const float4*)(xr + lane * 4 + i * 128);
        s  += v[i].x + v[i].y + v[i].z + v[i].w;
        s2 += v[i].x * v[i].x + v[i].y * v[i].y + v[i].z * v[i].z + v[i].w * v[i].w;
    }
#pragma unroll
    for (int off = 16; off; off >>= 1) {
        s  += __shfl_xor_sync(0xffffffffu, s, off);
        s2 += __shfl_xor_sync(0xffffffffu, s2, off);
    }
    float m = s * (1.f / DMODEL);
    float var = s2 * (1.f / DMODEL) - m * m;
    float rstd = rsqrtf(var + 1e-5f);
#pragma unroll
    for (int i = 0; i < 8; i++) {
        int c = lane * 4 + i * 128;
        float4 gv = *(const float4*)(g + c);
        float4 bv = *(const float4*)(b + c);
        float o0 = (v[i].x - m) * rstd * gv.x + bv.x;
        float o1 = (v[i].y - m) * rstd * gv.y + bv.y;
        float o2 = (v[i].z - m) * rstd * gv.z + bv.z;
        float o3 = (v[i].w - m) * rstd * gv.w + bv.w;
        if (HALF) {
            uint2 pk;
            pk.x = pack_h2(o0, o1);
            pk.y = pack_h2(o2, o3);
            *(uint2*)(oh + (size_t)row * DMODEL + c) = pk;
        } else {
            float4 o; o.x = o0; o.y = o1; o.z = o2; o.w = o3;
            *(float4*)(outf + (size_t)row * DMODEL + c) = o;
        }
    }
}

// ---------------- host ----------------
extern "C" void kernel_launch(void* const* d_in, const int* in_sizes, int n_in,
                              void* d_out, int out_size) {
    const int*   tokens = (const int*)  d_in[0];
    const int*   lengths= (const int*)  d_in[1];
    const float* emb    = (const float*)d_in[2];
    const float* Wq     = (const float*)d_in[3];
    const float* bq     = (const float*)d_in[4];
    const float* Wkv    = (const float*)d_in[5];
    const float* bkv    = (const float*)d_in[6];
    const float* Wo     = (const float*)d_in[7];
    const float* bo     = (const float*)d_in[8];
    const float* lag    = (const float*)d_in[9];
    const float* lab    = (const float*)d_in[10];
    const float* W1     = (const float*)d_in[11];
    const float* b1     = (const float*)d_in[12];
    const float* W2     = (const float*)d_in[13];
    const float* b2     = (const float*)d_in[14];
    const float* lfg    = (const float*)d_in[15];
    const float* lfb    = (const float*)d_in[16];
    const float* lng    = (const float*)d_in[17];
    const float* lnb    = (const float*)d_in[18];

    float *x, *pe, *bqkv;
    fp16 *qkv16, *h16, *o16, *f16;
    fp16 *wqkvT, *woT, *w1T, *w2T;
    cudaGetSymbolAddress((void**)&x, g_x);
    cudaGetSymbolAddress((void**)&pe, g_pe);
    cudaGetSymbolAddress((void**)&qkv16, g_qkv16);
    cudaGetSymbolAddress((void**)&h16, g_h16);
    cudaGetSymbolAddress((void**)&o16, g_o16);
    cudaGetSymbolAddress((void**)&f16, g_f16);
    cudaGetSymbolAddress((void**)&wqkvT, g_wqkvT);
    cudaGetSymbolAddress((void**)&woT, g_woT);
    cudaGetSymbolAddress((void**)&w1T, g_w1T);
    cudaGetSymbolAddress((void**)&w2T, g_w2T);
    cudaGetSymbolAddress((void**)&bqkv, g_bqkv);

    cudaFuncSetAttribute(tgemm<1>, cudaFuncAttributeMaxDynamicSharedMemorySize, SMEM_T);
    cudaFuncSetAttribute(tgemm<2>, cudaFuncAttributeMaxDynamicSharedMemorySize, SMEM_T);
    cudaFuncSetAttribute(tgemm<3>, cudaFuncAttributeMaxDynamicSharedMemorySize, SMEM_T);
    cudaFuncSetAttribute(fattn, cudaFuncAttributeMaxDynamicSharedMemorySize, FA_SMEM);

    dim3 tb(32, 8);
    wsplit<<<dim3(DMODEL / 32, DMODEL / 32, NLAYER), tb>>>(Wq,  wqkvT, DMODEL, DMODEL, QKVW, 0);
    wsplit<<<dim3(KVW / 32,    DMODEL / 32, NLAYER), tb>>>(Wkv, wqkvT, DMODEL, KVW,   QKVW, DMODEL);
    wsplit<<<dim3(DMODEL / 32, DMODEL / 32, NLAYER), tb>>>(Wo,  woT,   DMODEL, DMODEL, DMODEL, 0);
    wsplit<<<dim3(DFF / 32,    DMODEL / 32, NLAYER), tb>>>(W1,  w1T,   DMODEL, DFF,   DFF, 0);
    wsplit<<<dim3(DMODEL / 32, DFF / 32,    NLAYER), tb>>>(W2,  w2T,   DFF,    DMODEL, DMODEL, 0);
    bcat<<<(NLAYER * QKVW + 255) / 256, 256>>>(bq, bkv, bqkv);

    pe_kernel<<<(SEQ * DMODEL) / 256, 256>>>(pe);
    embed_kernel<<<(NTOK * DMODEL) / 256, 256>>>(tokens, emb, pe, x);

    for (int l = 0; l < NLAYER; l++) {
        size_t oQKV = (size_t)l * DMODEL * QKVW;
        size_t oO   = (size_t)l * DMODEL * DMODEL;
        size_t o1w  = (size_t)l * DMODEL * DFF;

        // attention sublayer
        ln_kernel<1><<<NTOK / 8, 256>>>(x, lag + l * DMODEL, lab + l * DMODEL, nullptr, h16);
        tgemm<3><<<dim3(QKVW / 256, NTOK / 128), 256, SMEM_T>>>(
            h16, wqkvT + oQKV, bqkv + l * QKVW, nullptr, qkv16, QKVW, DMODEL);
        fattn<<<dim3(SEQ / 128, BATCH * NHEAD), 256, FA_SMEM>>>(qkv16, lengths, o16);
        tgemm<1><<<dim3(DMODEL / 256, NTOK / 128), 256, SMEM_T>>>(
            o16, woT + oO, bo + l * DMODEL, x, nullptr, DMODEL, DMODEL);

        // FFN sublayer
        ln_kernel<1><<<NTOK / 8, 256>>>(x, lfg + l * DMODEL, lfb + l * DMODEL, nullptr, h16);
        tgemm<2><<<dim3(DFF / 256, NTOK / 128), 256, SMEM_T>>>(
            h16, w1T + o1w, b1 + l * DFF, nullptr, f16, DFF, DMODEL);
        tgemm<1><<<dim3(DMODEL / 256, NTOK / 128), 256, SMEM_T>>>(
            f16, w2T + o1w, b2 + l * DMODEL, x, nullptr, DMODEL, DFF);
    }

    ln_kernel<0><<<NTOK / 8, 256>>>(x, lng, lnb, (float*)d_out, nullptr);
}